// round 1
// baseline (speedup 1.0000x reference)
#include <cuda_runtime.h>
#include <cuda_fp16.h>
#include <math.h>

#define BATCH 4
#define CH    256
#define HH    100
#define WW    100
#define HWTOT (HH * WW)

// Scratch: x transposed to [B, H, W, C] in fp16. 4*10000*256*2 = 20.48 MB.
__device__ __half g_xt[(size_t)BATCH * HWTOT * CH];

// ---------------------------------------------------------------------------
// Kernel 1: [B,C,H,W] f32 -> [B,HW,C] fp16 via smem-tiled transpose.
// grid: (ceil(HW/32), C/32, B), block: (32, 8)
// ---------------------------------------------------------------------------
__global__ void transpose_f32_to_f16(const float* __restrict__ x) {
    __shared__ float tile[32][33];
    int b  = blockIdx.z;
    int c0 = blockIdx.y * 32;
    int s0 = blockIdx.x * 32;
    int tx = threadIdx.x, ty = threadIdx.y;
    const float* xb = x + (size_t)b * CH * HWTOT;
#pragma unroll
    for (int i = 0; i < 32; i += 8) {
        int s = s0 + tx;
        if (s < HWTOT)
            tile[ty + i][tx] = xb[(size_t)(c0 + ty + i) * HWTOT + s];
    }
    __syncthreads();
    __half* xtb = g_xt + (size_t)b * HWTOT * CH;
#pragma unroll
    for (int i = 0; i < 32; i += 8) {
        int s = s0 + ty + i;
        if (s < HWTOT)
            xtb[(size_t)s * CH + c0 + tx] = __float2half_rn(tile[tx][ty + i]);
    }
}

// ---------------------------------------------------------------------------
// Kernel 2: warp-per-pixel deformable sample + max + dot + sigmoid.
// lane covers channels [lane*8, lane*8+8): one LDG.128 of 8 halves per corner.
// ---------------------------------------------------------------------------
__device__ __forceinline__ void corner_acc(float samp[8], const __half* p, float wgt) {
    uint4 u = __ldg((const uint4*)p);
    float2 f0 = __half22float2(*(const __half2*)&u.x);
    float2 f1 = __half22float2(*(const __half2*)&u.y);
    float2 f2 = __half22float2(*(const __half2*)&u.z);
    float2 f3 = __half22float2(*(const __half2*)&u.w);
    samp[0] = fmaf(wgt, f0.x, samp[0]);
    samp[1] = fmaf(wgt, f0.y, samp[1]);
    samp[2] = fmaf(wgt, f1.x, samp[2]);
    samp[3] = fmaf(wgt, f1.y, samp[3]);
    samp[4] = fmaf(wgt, f2.x, samp[4]);
    samp[5] = fmaf(wgt, f2.y, samp[5]);
    samp[6] = fmaf(wgt, f3.x, samp[6]);
    samp[7] = fmaf(wgt, f3.y, samp[7]);
}

__global__ __launch_bounds__(256) void dsa_main(
    const float* __restrict__ offset, const float* __restrict__ w0,
    const float* __restrict__ b0, float* __restrict__ out)
{
    int warpId = threadIdx.x >> 5;
    int lane   = threadIdx.x & 31;
    int p  = blockIdx.x * 8 + warpId;           // pixel id, 0..39999
    int b  = p / HWTOT;
    int hw = p - b * HWTOT;
    int h  = hw / WW;
    int w  = hw - h * WW;
    int c0 = lane * 8;

    const __half* xb   = g_xt + (size_t)b * HWTOT * CH + c0;
    const float*  offb = offset + (size_t)b * 18 * HWTOT + hw;

    float feat[8];
#pragma unroll
    for (int j = 0; j < 8; j++) feat[j] = -__int_as_float(0x7f800000); // -inf

#pragma unroll
    for (int k = 0; k < 9; k++) {
        float offy = __ldg(offb + (2 * k) * HWTOT);
        float offx = __ldg(offb + (2 * k + 1) * HWTOT);
        float py = (float)(h + (k / 3) - 1) + offy;
        float px = (float)(w + (k % 3) - 1) + offx;
        float y0f = floorf(py), x0f = floorf(px);
        float wy = py - y0f, wx = px - x0f;
        int y0 = (int)y0f, x0 = (int)x0f;
        int y1 = y0 + 1,   x1 = x0 + 1;
        bool vy0 = (unsigned)y0 < (unsigned)HH;
        bool vy1 = (unsigned)y1 < (unsigned)HH;
        bool vx0 = (unsigned)x0 < (unsigned)WW;
        bool vx1 = (unsigned)x1 < (unsigned)WW;
        float w00 = (1.f - wy) * (1.f - wx); if (!(vy0 && vx0)) w00 = 0.f;
        float w01 = (1.f - wy) * wx;         if (!(vy0 && vx1)) w01 = 0.f;
        float w10 = wy * (1.f - wx);         if (!(vy1 && vx0)) w10 = 0.f;
        float w11 = wy * wx;                 if (!(vy1 && vx1)) w11 = 0.f;
        int yc0 = min(max(y0, 0), HH - 1), yc1 = min(max(y1, 0), HH - 1);
        int xc0 = min(max(x0, 0), WW - 1), xc1 = min(max(x1, 0), WW - 1);

        float samp[8] = {0.f, 0.f, 0.f, 0.f, 0.f, 0.f, 0.f, 0.f};
        corner_acc(samp, xb + (size_t)(yc0 * WW + xc0) * CH, w00);
        corner_acc(samp, xb + (size_t)(yc0 * WW + xc1) * CH, w01);
        corner_acc(samp, xb + (size_t)(yc1 * WW + xc0) * CH, w10);
        corner_acc(samp, xb + (size_t)(yc1 * WW + xc1) * CH, w11);
#pragma unroll
        for (int j = 0; j < 8; j++) feat[j] = fmaxf(feat[j], samp[j]);
    }

    float4 wa  = __ldg((const float4*)(w0 + c0));
    float4 wb2 = __ldg((const float4*)(w0 + c0 + 4));
    float acc = wa.x * feat[0] + wa.y * feat[1] + wa.z * feat[2] + wa.w * feat[3]
              + wb2.x * feat[4] + wb2.y * feat[5] + wb2.z * feat[6] + wb2.w * feat[7];
#pragma unroll
    for (int s = 16; s > 0; s >>= 1)
        acc += __shfl_xor_sync(0xffffffffu, acc, s);
    if (lane == 0) {
        float v = acc + __ldg(b0);
        out[p] = 1.f / (1.f + expf(-v));
    }
}

// ---------------------------------------------------------------------------
extern "C" void kernel_launch(void* const* d_in, const int* in_sizes, int n_in,
                              void* d_out, int out_size)
{
    const float *x = nullptr, *offset = nullptr, *w0 = nullptr, *b0 = nullptr;
    for (int i = 0; i < n_in; i++) {
        if      (in_sizes[i] == BATCH * CH * HWTOT) x      = (const float*)d_in[i];
        else if (in_sizes[i] == BATCH * 18 * HWTOT) offset = (const float*)d_in[i];
        else if (in_sizes[i] == CH)                 w0     = (const float*)d_in[i];
        else if (in_sizes[i] == 1)                  b0     = (const float*)d_in[i];
    }

    dim3 tb(32, 8);
    dim3 tg((HWTOT + 31) / 32, CH / 32, BATCH);
    transpose_f32_to_f16<<<tg, tb>>>(x);

    dsa_main<<<(BATCH * HWTOT) / 8, 256>>>(offset, w0, b0, (float*)d_out);
}